// round 10
// baseline (speedup 1.0000x reference)
#include <cuda_runtime.h>
#include <cuda_fp16.h>
#include <cstdint>
#include <math.h>

#define B_   2
#define S_   2048
#define DIN_ 2048
#define H_   32
#define G_   8
#define D_   64
#define M_   (B_*S_)

#define OUT_ELEMS ((size_t)B_*S_*DIN_)
#define KV_ELEMS  ((size_t)B_*G_*S_*D_)

// ---------------- scratch ----------------
__device__ __half g_xh   [(size_t)M_*DIN_];
__device__ __half g_Wqkvt[(size_t)(H_*D_ + 2*G_*D_)*DIN_];
__device__ __half g_Wot  [(size_t)DIN_*H_*D_];
__device__ float  g_Qf   [(size_t)B_*H_*S_*D_];
__device__ __half g_Qh   [(size_t)B_*H_*S_*D_];   // pre-scaled by log2e/8
__device__ __half g_Kh   [KV_ELEMS];
__device__ __half g_Vt   [KV_ELEMS];              // (b,g,d,s)
__device__ __half g_ctxh [(size_t)M_*H_*D_];

// ---------------- PTX helpers ----------------
__device__ __forceinline__ void cp16(void* s, const void* g){
    uint32_t sa = (uint32_t)__cvta_generic_to_shared(s);
    asm volatile("cp.async.cg.shared.global [%0], [%1], 16;\n" :: "r"(sa), "l"(g));
}
__device__ __forceinline__ void cp_commit(){ asm volatile("cp.async.commit_group;\n"); }
template<int N> __device__ __forceinline__ void cp_wait(){
    asm volatile("cp.async.wait_group %0;\n" :: "n"(N));
}
__device__ __forceinline__ void mma16816(float* c, const uint32_t* a, const uint32_t* b){
    asm volatile("mma.sync.aligned.m16n8k16.row.col.f32.f16.f16.f32 "
        "{%0,%1,%2,%3},{%4,%5,%6,%7},{%8,%9},{%0,%1,%2,%3};\n"
        : "+f"(c[0]),"+f"(c[1]),"+f"(c[2]),"+f"(c[3])
        : "r"(a[0]),"r"(a[1]),"r"(a[2]),"r"(a[3]),"r"(b[0]),"r"(b[1]));
}
__device__ __forceinline__ void ldsm4(uint32_t* r, const __half* p){
    uint32_t a = (uint32_t)__cvta_generic_to_shared(p);
    asm volatile("ldmatrix.sync.aligned.m8n8.x4.shared.b16 {%0,%1,%2,%3}, [%4];"
        : "=r"(r[0]),"=r"(r[1]),"=r"(r[2]),"=r"(r[3]) : "r"(a));
}
__device__ __forceinline__ uint32_t ex2h2(float lo, float hi){
    uint32_t r;
    asm("{\n\t.reg .b32 t;\n\t"
        "cvt.rn.f16x2.f32 t, %2, %1;\n\t"
        "ex2.approx.f16x2 %0, t;\n\t}"
        : "=r"(r) : "f"(lo), "f"(hi));
    return r;
}

// ---------------- conversion kernels ----------------
__global__ void f2h_kernel(const float* __restrict__ in, __half* __restrict__ out, int n4){
    int i = blockIdx.x * blockDim.x + threadIdx.x;
    if (i >= n4) return;
    float4 v = *(const float4*)(in + (size_t)i*4);
    __half* o = out + (size_t)i*4;
    o[0]=__float2half_rn(v.x); o[1]=__float2half_rn(v.y);
    o[2]=__float2half_rn(v.z); o[3]=__float2half_rn(v.w);
}

__global__ void wtrans_kernel(const float* __restrict__ W, __half* __restrict__ Wt, int K, int N){
    __shared__ float t[32][33];
    int n0 = blockIdx.x*32, k0 = blockIdx.y*32;
    for (int j = threadIdx.y; j < 32; j += 8)
        t[j][threadIdx.x] = W[(size_t)(k0+j)*N + n0 + threadIdx.x];
    __syncthreads();
    for (int j = threadIdx.y; j < 32; j += 8)
        Wt[(size_t)(n0+j)*K + k0 + threadIdx.x] = __float2half_rn(t[threadIdx.x][j]);
}

__global__ void vtrans_kernel(const float* __restrict__ V, __half* __restrict__ Vt){
    __shared__ float t[32][33];
    int s0 = blockIdx.x*32, d0 = blockIdx.y*32, bg = blockIdx.z;
    const float* Vb = V + (size_t)bg*S_*D_;
    __half* Vo = Vt + (size_t)bg*S_*D_;
    for (int j = threadIdx.y; j < 32; j += 8)
        t[j][threadIdx.x] = Vb[(size_t)(s0+j)*D_ + d0 + threadIdx.x];
    __syncthreads();
    for (int j = threadIdx.y; j < 32; j += 8)
        Vo[(size_t)(d0+j)*S_ + s0 + threadIdx.x] = __float2half_rn(t[threadIdx.x][j]);
}

// ---------------- HGEMM: 8 warps, 64x32 warp tiles, 4-stage cp.async, 1 bar/iter ----------------
#define GBM 128
#define GBN 128
#define GBK 32
#define GST 40
#define GSTAGES 4

__global__ __launch_bounds__(256,2) void hgemm_kernel(
    const __half* __restrict__ A, const __half* __restrict__ Bt,
    float* __restrict__ C, float* __restrict__ Ck, float* __restrict__ Cv,
    int Ndim, int Kdim, int mode)
{
    extern __shared__ __half hs[];
    __half* As = hs;
    __half* Bs = hs + GSTAGES*GBM*GST;

    const int tid = threadIdx.x, lane = tid & 31, wid = tid >> 5;
    const int wm = (wid & 1) * 64, wn = (wid >> 1) * 32;
    const int bm = blockIdx.y * GBM, bn = blockIdx.x * GBN;

    const int ldRow = tid >> 1;
    const int ldOff = (tid & 1) * 16;
    const __half* Ap = A  + (size_t)(bm + ldRow) * Kdim + ldOff;
    const __half* Bp = Bt + (size_t)(bn + ldRow) * Kdim + ldOff;

    const int l16 = lane & 15, lh = lane >> 4;
    const int g8h = lane >> 3, l8 = lane & 7;

    float acc[4][4][4];
    #pragma unroll
    for (int mi=0; mi<4; mi++)
        #pragma unroll
        for (int ni=0; ni<4; ni++)
            #pragma unroll
            for (int r=0; r<4; r++) acc[mi][ni][r] = 0.f;

    const int nk = Kdim / GBK;
    #pragma unroll
    for (int s = 0; s < 3; s++){
        int k0 = s * GBK;
        cp16(&As[(s*GBM + ldRow)*GST + ldOff],     Ap + k0);
        cp16(&As[(s*GBM + ldRow)*GST + ldOff + 8], Ap + k0 + 8);
        cp16(&Bs[(s*GBN + ldRow)*GST + ldOff],     Bp + k0);
        cp16(&Bs[(s*GBN + ldRow)*GST + ldOff + 8], Bp + k0 + 8);
        cp_commit();
    }

    for (int it = 0; it < nk; ++it){
        const int st = it % GSTAGES;
        if (it == nk - 1)      cp_wait<0>();
        else if (it == nk - 2) cp_wait<1>();
        else                   cp_wait<2>();
        __syncthreads();
        if (it + 3 < nk){
            int sn = (it + 3) % GSTAGES;
            int k0 = (it + 3) * GBK;
            cp16(&As[(sn*GBM + ldRow)*GST + ldOff],     Ap + k0);
            cp16(&As[(sn*GBM + ldRow)*GST + ldOff + 8], Ap + k0 + 8);
            cp16(&Bs[(sn*GBN + ldRow)*GST + ldOff],     Bp + k0);
            cp16(&Bs[(sn*GBN + ldRow)*GST + ldOff + 8], Bp + k0 + 8);
            cp_commit();
        }

        #pragma unroll
        for (int ks = 0; ks < 2; ks++){
            const int kk = ks * 16;
            uint32_t a[4][4], bq[2][4];
            #pragma unroll
            for (int mi = 0; mi < 4; mi++)
                ldsm4(a[mi], &As[(st*GBM + wm + mi*16 + l16)*GST + kk + lh*8]);
            #pragma unroll
            for (int ni2 = 0; ni2 < 2; ni2++)
                ldsm4(bq[ni2], &Bs[(st*GBN + wn + ni2*16 + (g8h>>1)*8 + l8)*GST + kk + (g8h&1)*8]);
            #pragma unroll
            for (int mi = 0; mi < 4; mi++)
                #pragma unroll
                for (int ni = 0; ni < 4; ni++)
                    mma16816(acc[mi][ni], a[mi], &bq[ni>>1][(ni&1)*2]);
        }
        // NOTE: no trailing barrier. Writer at iter it targets stage (it+3)%4 ==
        // (it-1)%4; the top barrier of iter it already guarantees all warps
        // finished computing iter it-1.
    }

    if (mode == 0){
        #pragma unroll
        for (int mi = 0; mi < 4; mi++)
            #pragma unroll
            for (int ni = 0; ni < 4; ni++){
                int r = bm + wm + mi*16 + (lane >> 2);
                int c = bn + wn + ni*8 + (lane & 3)*2;
                *(float2*)&C[(size_t)r*Ndim + c]     = make_float2(acc[mi][ni][0], acc[mi][ni][1]);
                *(float2*)&C[(size_t)(r+8)*Ndim + c] = make_float2(acc[mi][ni][2], acc[mi][ni][3]);
            }
    } else {
        float* T; int nb, Hn;
        if (bn < 2048)      { T = C;  nb = 0;    Hn = 32; }
        else if (bn < 2560) { T = Ck; nb = 2048; Hn = 8;  }
        else                { T = Cv; nb = 2560; Hn = 8;  }
        #pragma unroll
        for (int mi = 0; mi < 4; mi++)
            #pragma unroll
            for (int ni = 0; ni < 4; ni++){
                int r = bm + wm + mi*16 + (lane >> 2);
                int c = bn + wn + ni*8 + (lane & 3)*2 - nb;
                int bb = r >> 11;
                int hh = c >> 6, dd = c & 63;
                size_t base = (((size_t)bb*Hn + hh)*S_ + (r & (S_-1)))*D_ + dd;
                *(float2*)&T[base] = make_float2(acc[mi][ni][0], acc[mi][ni][1]);
                size_t base2 = (((size_t)bb*Hn + hh)*S_ + ((r+8) & (S_-1)))*D_ + dd;
                *(float2*)&T[base2] = make_float2(acc[mi][ni][2], acc[mi][ni][3]);
            }
    }
}

// ---------------- fused RMSNorm + RoPE ----------------
__global__ void rmsrope2_kernel(const float* __restrict__ in, float* __restrict__ outf,
                                __half* __restrict__ outh,
                                const float* __restrict__ cosp, const float* __restrict__ sinp,
                                const float* __restrict__ scale, int totalRows, float mult)
{
    int row  = blockIdx.x * (blockDim.x >> 5) + (threadIdx.x >> 5);
    int lane = threadIdx.x & 31;
    if (row >= totalRows) return;
    int s = row & (S_ - 1);
    const float* p = in + (size_t)row * D_;
    float v1 = p[lane], v2 = p[lane + 32];
    float ss = v1*v1 + v2*v2;
    #pragma unroll
    for (int o = 16; o > 0; o >>= 1) ss += __shfl_xor_sync(0xffffffffu, ss, o);
    float inv = rsqrtf(ss * (1.0f/64.0f) + 1e-6f);
    float n1 = v1 * inv * scale[lane];
    float n2 = v2 * inv * scale[lane + 32];
    float c1 = cosp[s*D_ + lane],      s1 = sinp[s*D_ + lane];
    float c2 = cosp[s*D_ + lane + 32], s2 = sinp[s*D_ + lane + 32];
    float o1 = n1*c1 - n2*s1;
    float o2 = n2*c2 + n1*s2;
    if (outf){
        outf[(size_t)row*D_ + lane]      = o1;
        outf[(size_t)row*D_ + lane + 32] = o2;
    }
    outh[(size_t)row*D_ + lane]      = __float2half_rn(o1 * mult);
    outh[(size_t)row*D_ + lane + 32] = __float2half_rn(o2 * mult);
}

// ---------------- FA2 attention: 4-stage, LPT block order ----------------
#define AQP 72
#define VROWS 80
#define ASTAGES 4

__global__ __launch_bounds__(256) void attn3_kernel(
    const __half* __restrict__ Qh, const __half* __restrict__ Kh,
    const __half* __restrict__ Vt, __half* __restrict__ CTX)
{
    extern __shared__ char smraw[];
    __half* Qs = (__half*)smraw;               // [128][AQP]
    __half* Ks = Qs + 128*AQP;                 // [4][64][AQP]
    __half* Vs = Ks + ASTAGES*64*AQP;          // [4][VROWS][AQP]

    const int tid = threadIdx.x, lane = tid & 31, w = tid >> 5;
    const int l16 = lane & 15, lh = lane >> 4;
    const int g8h = lane >> 3, l8 = lane & 7;

    // LPT: heaviest q-tiles (largest qt) launch first
    const int qt = (int)gridDim.x - 1 - (int)blockIdx.x;
    const int bh = blockIdx.y;
    const int b = bh >> 5, h = bh & 31, g = h >> 2;

    const __half* Qbase = Qh + (((size_t)b*H_ + h)*S_ + (size_t)qt*128) * D_;
    const __half* Kbase = Kh + ((size_t)b*G_ + g) * (size_t)S_ * D_;
    const __half* Vbase = Vt + ((size_t)b*G_ + g) * (size_t)D_ * S_;

    const int nkt = 2*qt + 2;

    // ones/zeros pad rows of Vs (all stages)
    for (int idx = tid; idx < ASTAGES*16*AQP; idx += 256){
        int s  = idx / (16*AQP);
        int rm = idx % (16*AQP);
        int r  = rm / AQP, c = rm % AQP;
        Vs[((size_t)s*VROWS + 64 + r)*AQP + c] = (r == 0) ? __float2half(1.f) : __float2half(0.f);
    }

    // prologue: Q (1 group) + up to 3 K/V tiles (1 group each)
    {
        int r = tid >> 1, c0 = (tid & 1) * 32;
        const __half* qp = Qbase + (size_t)r*D_ + c0;
        cp16(&Qs[r*AQP + c0],      qp);
        cp16(&Qs[r*AQP + c0 + 8],  qp + 8);
        cp16(&Qs[r*AQP + c0 + 16], qp + 16);
        cp16(&Qs[r*AQP + c0 + 24], qp + 24);
        cp_commit();
        int r2 = tid >> 2, c2 = (tid & 3) * 16;
        int npre = nkt < 3 ? nkt : 3;
        for (int t = 0; t < npre; t++){
            const __half* kp = Kbase + ((size_t)t*64 + r2)*D_ + c2;
            cp16(&Ks[(t*64 + r2)*AQP + c2],     kp);
            cp16(&Ks[(t*64 + r2)*AQP + c2 + 8], kp + 8);
            const __half* vp = Vbase + (size_t)r2*S_ + (size_t)t*64 + c2;
            cp16(&Vs[(t*VROWS + r2)*AQP + c2],     vp);
            cp16(&Vs[(t*VROWS + r2)*AQP + c2 + 8], vp + 8);
            cp_commit();
        }
    }
    if (nkt >= 3) cp_wait<3>(); else cp_wait<2>();   // ensure Q landed
    __syncthreads();

    uint32_t qa[4][4];
    #pragma unroll
    for (int ks = 0; ks < 4; ks++)
        ldsm4(qa[ks], &Qs[(w*16 + l16)*AQP + ks*16 + lh*8]);

    float o[9][4];   // o[8] = row-sum accumulator
    #pragma unroll
    for (int j = 0; j < 9; j++)
        #pragma unroll
        for (int r = 0; r < 4; r++) o[j][r] = 0.f;
    float m0 = -1e30f, m1 = -1e30f;

    const int qmin = qt*128 + w*16;
    const int r2 = tid >> 2, c2l = (tid & 3) * 16;

    for (int kt = 0; kt < nkt; ++kt){
        const int st = kt % ASTAGES;
        if (kt == nkt - 1)      cp_wait<0>();
        else if (kt == nkt - 2) cp_wait<1>();
        else                    cp_wait<2>();
        __syncthreads();
        if (kt + 3 < nkt){
            int sn = (kt + 3) % ASTAGES;
            const __half* kp = Kbase + ((size_t)(kt+3)*64 + r2)*D_ + c2l;
            cp16(&Ks[(sn*64 + r2)*AQP + c2l],     kp);
            cp16(&Ks[(sn*64 + r2)*AQP + c2l + 8], kp + 8);
            const __half* vp = Vbase + (size_t)r2*S_ + (size_t)(kt+3)*64 + c2l;
            cp16(&Vs[(sn*VROWS + r2)*AQP + c2l],     vp);
            cp16(&Vs[(sn*VROWS + r2)*AQP + c2l + 8], vp + 8);
            cp_commit();
        }

        if (kt*64 <= qmin + 15){
            float sc[8][4];
            #pragma unroll
            for (int j = 0; j < 8; j++)
                #pragma unroll
                for (int r = 0; r < 4; r++) sc[j][r] = 0.f;

            #pragma unroll
            for (int ks = 0; ks < 4; ks++){
                uint32_t bq[4][4];
                #pragma unroll
                for (int nt2 = 0; nt2 < 4; nt2++)
                    ldsm4(bq[nt2], &Ks[(st*64 + nt2*16 + (g8h>>1)*8 + l8)*AQP + ks*16 + (g8h&1)*8]);
                #pragma unroll
                for (int j = 0; j < 8; j++)
                    mma16816(sc[j], qa[ks], &bq[j>>1][(j&1)*2]);
            }

            const int qg0 = qmin + (lane >> 2);
            if (kt*64 + 63 > qmin){
                #pragma unroll
                for (int j = 0; j < 8; j++){
                    int kg = kt*64 + j*8 + (lane & 3)*2;
                    if (kg     > qg0    ) sc[j][0] = -1e30f;
                    if (kg + 1 > qg0    ) sc[j][1] = -1e30f;
                    if (kg     > qg0 + 8) sc[j][2] = -1e30f;
                    if (kg + 1 > qg0 + 8) sc[j][3] = -1e30f;
                }
            }

            float mx0 = -1e30f, mx1 = -1e30f;
            #pragma unroll
            for (int j = 0; j < 8; j++){
                mx0 = fmaxf(mx0, fmaxf(sc[j][0], sc[j][1]));
                mx1 = fmaxf(mx1, fmaxf(sc[j][2], sc[j][3]));
            }
            mx0 = fmaxf(mx0, __shfl_xor_sync(0xffffffffu, mx0, 1));
            mx0 = fmaxf(mx0, __shfl_xor_sync(0xffffffffu, mx0, 2));
            mx1 = fmaxf(mx1, __shfl_xor_sync(0xffffffffu, mx1, 1));
            mx1 = fmaxf(mx1, __shfl_xor_sync(0xffffffffu, mx1, 2));
            float mn0 = fmaxf(m0, mx0), mn1 = fmaxf(m1, mx1);
            float al0 = exp2f(m0 - mn0), al1 = exp2f(m1 - mn1);
            m0 = mn0; m1 = mn1;

            uint32_t pa[4][4];
            #pragma unroll
            for (int j = 0; j < 8; j++){
                int ks = j >> 1, hi = (j & 1) * 2;
                pa[ks][hi]     = ex2h2(sc[j][0] - mn0, sc[j][1] - mn0);
                pa[ks][hi + 1] = ex2h2(sc[j][2] - mn1, sc[j][3] - mn1);
            }

            #pragma unroll
            for (int j = 0; j < 9; j++){
                o[j][0] *= al0; o[j][1] *= al0;
                o[j][2] *= al1; o[j][3] *= al1;
            }

            #pragma unroll
            for (int ks = 0; ks < 4; ks++){
                uint32_t bv[4][4], bone[4];
                #pragma unroll
                for (int nt2 = 0; nt2 < 4; nt2++)
                    ldsm4(bv[nt2], &Vs[(st*VROWS + nt2*16 + (g8h>>1)*8 + l8)*AQP + ks*16 + (g8h&1)*8]);
                ldsm4(bone, &Vs[(st*VROWS + 64 + (g8h>>1)*8 + l8)*AQP + ks*16 + (g8h&1)*8]);
                #pragma unroll
                for (int j = 0; j < 8; j++)
                    mma16816(o[j], pa[ks], &bv[j>>1][(j&1)*2]);
                mma16816(o[8], pa[ks], &bone[0]);
            }
        }
    }

    int src = lane & ~3;
    float l0 = __shfl_sync(0xffffffffu, o[8][0], src);
    float l1 = __shfl_sync(0xffffffffu, o[8][2], src);
    float i0 = 1.0f / l0, i1 = 1.0f / l1;

    const int q0 = w*16 + (lane >> 2);
    const int sg0 = qt*128 + q0;
    #pragma unroll
    for (int j = 0; j < 8; j++){
        int d = j*8 + (lane & 3)*2;
        __half2 hA = __halves2half2(__float2half_rn(o[j][0]*i0), __float2half_rn(o[j][1]*i0));
        __half2 hB = __halves2half2(__float2half_rn(o[j][2]*i1), __float2half_rn(o[j][3]*i1));
        *(__half2*)&CTX[(((size_t)b*S_ + sg0    )*H_ + h)*D_ + d] = hA;
        *(__half2*)&CTX[(((size_t)b*S_ + sg0 + 8)*H_ + h)*D_ + d] = hB;
    }
}

// ---------------- launch ----------------
extern "C" void kernel_launch(void* const* d_in, const int* in_sizes, int n_in,
                              void* d_out, int out_size)
{
    const float* x      = (const float*)d_in[0];
    const float* cosp   = (const float*)d_in[2];
    const float* sinp   = (const float*)d_in[3];
    const float* Wq     = (const float*)d_in[4];
    const float* Wk     = (const float*)d_in[5];
    const float* Wv     = (const float*)d_in[6];
    const float* Wo     = (const float*)d_in[7];
    const float* qscale = (const float*)d_in[8];
    const float* kscale = (const float*)d_in[9];

    float* out  = (float*)d_out;
    float* Kout = out + OUT_ELEMS;
    float* Vout = Kout + KV_ELEMS;

    __half *xh, *Wqkvt, *Wot, *Qh, *Kh, *Vt, *ctxh;
    float *Qf;
    cudaGetSymbolAddress((void**)&xh,    g_xh);
    cudaGetSymbolAddress((void**)&Wqkvt, g_Wqkvt);
    cudaGetSymbolAddress((void**)&Wot,   g_Wot);
    cudaGetSymbolAddress((void**)&Qf,    g_Qf);
    cudaGetSymbolAddress((void**)&Qh,    g_Qh);
    cudaGetSymbolAddress((void**)&Kh,    g_Kh);
    cudaGetSymbolAddress((void**)&Vt,    g_Vt);
    cudaGetSymbolAddress((void**)&ctxh,  g_ctxh);

    const int gemmSmem = 2 * GSTAGES * GBM * GST * (int)sizeof(__half);  // 81920
    cudaFuncSetAttribute(hgemm_kernel, cudaFuncAttributeMaxDynamicSharedMemorySize, gemmSmem);

    {
        int n4 = (M_*DIN_)/4;
        f2h_kernel<<<(n4+255)/256, 256>>>(x, xh, n4);
        dim3 tb(32,8);
        wtrans_kernel<<<dim3((H_*D_)/32, DIN_/32), tb>>>(Wq, Wqkvt,                     DIN_, H_*D_);
        wtrans_kernel<<<dim3((G_*D_)/32, DIN_/32), tb>>>(Wk, Wqkvt + (size_t)2048*DIN_, DIN_, G_*D_);
        wtrans_kernel<<<dim3((G_*D_)/32, DIN_/32), tb>>>(Wv, Wqkvt + (size_t)2560*DIN_, DIN_, G_*D_);
        wtrans_kernel<<<dim3(DIN_/32, (H_*D_)/32), tb>>>(Wo, Wot, H_*D_, DIN_);
    }

    // fused QKV projection
    hgemm_kernel<<<dim3(3072/GBN, M_/GBM), 256, gemmSmem>>>(xh, Wqkvt, Qf, Kout, Vout, 3072, DIN_, 2);

    // rmsnorm + rope; Q additionally scaled by log2e/sqrt(D)
    rmsrope2_kernel<<<(B_*H_*S_)/8, 256>>>(Qf, nullptr, Qh, cosp, sinp, qscale, B_*H_*S_, 0.125f*1.44269504089f);
    rmsrope2_kernel<<<(B_*G_*S_)/8, 256>>>(Kout, Kout, Kh, cosp, sinp, kscale, B_*G_*S_, 1.0f);
    vtrans_kernel<<<dim3(S_/32, D_/32, B_*G_), dim3(32,8)>>>(Vout, Vt);

    // attention
    {
        int smem = (128*AQP + ASTAGES*64*AQP + ASTAGES*VROWS*AQP) * (int)sizeof(__half);  // 101376
        cudaFuncSetAttribute(attn3_kernel, cudaFuncAttributeMaxDynamicSharedMemorySize, smem);
        attn3_kernel<<<dim3(S_/128, B_*H_), 256, smem>>>(Qh, Kh, Vt, ctxh);
    }

    // output projection
    hgemm_kernel<<<dim3(DIN_/GBN, M_/GBM), 256, gemmSmem>>>(ctxh, Wot, out, nullptr, nullptr, DIN_, H_*D_, 0);
}

// round 17
// speedup vs baseline: 1.0169x; 1.0169x over previous
#include <cuda_runtime.h>
#include <cuda_fp16.h>
#include <cstdint>
#include <math.h>

#define B_   2
#define S_   2048
#define DIN_ 2048
#define H_   32
#define G_   8
#define D_   64
#define M_   (B_*S_)

#define OUT_ELEMS ((size_t)B_*S_*DIN_)
#define KV_ELEMS  ((size_t)B_*G_*S_*D_)

// ---------------- scratch ----------------
__device__ __half g_xh   [(size_t)M_*DIN_];
__device__ __half g_Wqkvt[(size_t)(H_*D_ + 2*G_*D_)*DIN_];
__device__ __half g_Wot  [(size_t)DIN_*H_*D_];
__device__ __half g_Qraw [(size_t)B_*H_*S_*D_];   // half, pre-rmsnorm q
__device__ __half g_Qh   [(size_t)B_*H_*S_*D_];   // half, post rms+rope, * log2e/8
__device__ __half g_Kh   [KV_ELEMS];
__device__ __half g_Vt   [KV_ELEMS];              // (b,g,d,s)
__device__ __half g_ctxh [(size_t)M_*H_*D_];

// ---------------- PTX helpers ----------------
__device__ __forceinline__ void cp16(void* s, const void* g){
    uint32_t sa = (uint32_t)__cvta_generic_to_shared(s);
    asm volatile("cp.async.cg.shared.global [%0], [%1], 16;\n" :: "r"(sa), "l"(g));
}
__device__ __forceinline__ void cp_commit(){ asm volatile("cp.async.commit_group;\n"); }
template<int N> __device__ __forceinline__ void cp_wait(){
    asm volatile("cp.async.wait_group %0;\n" :: "n"(N));
}
__device__ __forceinline__ void mma16816(float* c, const uint32_t* a, const uint32_t* b){
    asm volatile("mma.sync.aligned.m16n8k16.row.col.f32.f16.f16.f32 "
        "{%0,%1,%2,%3},{%4,%5,%6,%7},{%8,%9},{%0,%1,%2,%3};\n"
        : "+f"(c[0]),"+f"(c[1]),"+f"(c[2]),"+f"(c[3])
        : "r"(a[0]),"r"(a[1]),"r"(a[2]),"r"(a[3]),"r"(b[0]),"r"(b[1]));
}
__device__ __forceinline__ void ldsm4(uint32_t* r, const __half* p){
    uint32_t a = (uint32_t)__cvta_generic_to_shared(p);
    asm volatile("ldmatrix.sync.aligned.m8n8.x4.shared.b16 {%0,%1,%2,%3}, [%4];"
        : "=r"(r[0]),"=r"(r[1]),"=r"(r[2]),"=r"(r[3]) : "r"(a));
}
__device__ __forceinline__ uint32_t ex2h2(float lo, float hi){
    uint32_t r;
    asm("{\n\t.reg .b32 t;\n\t"
        "cvt.rn.f16x2.f32 t, %2, %1;\n\t"
        "ex2.approx.f16x2 %0, t;\n\t}"
        : "=r"(r) : "f"(lo), "f"(hi));
    return r;
}

// ---------------- conversion kernels ----------------
__global__ void f2h_kernel(const float* __restrict__ in, __half* __restrict__ out, int n4){
    int i = blockIdx.x * blockDim.x + threadIdx.x;
    if (i >= n4) return;
    float4 v = *(const float4*)(in + (size_t)i*4);
    __half* o = out + (size_t)i*4;
    o[0]=__float2half_rn(v.x); o[1]=__float2half_rn(v.y);
    o[2]=__float2half_rn(v.z); o[3]=__float2half_rn(v.w);
}

__global__ void wtrans_kernel(const float* __restrict__ W, __half* __restrict__ Wt, int K, int N){
    __shared__ float t[32][33];
    int n0 = blockIdx.x*32, k0 = blockIdx.y*32;
    for (int j = threadIdx.y; j < 32; j += 8)
        t[j][threadIdx.x] = W[(size_t)(k0+j)*N + n0 + threadIdx.x];
    __syncthreads();
    for (int j = threadIdx.y; j < 32; j += 8)
        Wt[(size_t)(n0+j)*K + k0 + threadIdx.x] = __float2half_rn(t[threadIdx.x][j]);
}

__global__ void vtrans_kernel(const float* __restrict__ V, __half* __restrict__ Vt){
    __shared__ float t[32][33];
    int s0 = blockIdx.x*32, d0 = blockIdx.y*32, bg = blockIdx.z;
    const float* Vb = V + (size_t)bg*S_*D_;
    __half* Vo = Vt + (size_t)bg*S_*D_;
    for (int j = threadIdx.y; j < 32; j += 8)
        t[j][threadIdx.x] = Vb[(size_t)(s0+j)*D_ + d0 + threadIdx.x];
    __syncthreads();
    for (int j = threadIdx.y; j < 32; j += 8)
        Vo[(size_t)(d0+j)*S_ + s0 + threadIdx.x] = __float2half_rn(t[threadIdx.x][j]);
}

// ---------------- HGEMM: 8 warps, 64x32 warp tiles, 4-stage cp.async, 1 bar/iter ----------------
#define GBM 128
#define GBN 128
#define GBK 32
#define GST 40
#define GSTAGES 4

// mode 0: plain row-major C
// mode 2: fused QKV: Q region -> HALF headed(32) into Cq; K/V regions -> float headed(8)
__global__ __launch_bounds__(256,2) void hgemm_kernel(
    const __half* __restrict__ A, const __half* __restrict__ Bt,
    float* __restrict__ C, float* __restrict__ Ck, float* __restrict__ Cv,
    __half* __restrict__ Cq,
    int Ndim, int Kdim, int mode)
{
    extern __shared__ __half hs[];
    __half* As = hs;
    __half* Bs = hs + GSTAGES*GBM*GST;

    const int tid = threadIdx.x, lane = tid & 31, wid = tid >> 5;
    const int wm = (wid & 1) * 64, wn = (wid >> 1) * 32;
    const int bm = blockIdx.y * GBM, bn = blockIdx.x * GBN;

    const int ldRow = tid >> 1;
    const int ldOff = (tid & 1) * 16;
    const __half* Ap = A  + (size_t)(bm + ldRow) * Kdim + ldOff;
    const __half* Bp = Bt + (size_t)(bn + ldRow) * Kdim + ldOff;

    const int l16 = lane & 15, lh = lane >> 4;
    const int g8h = lane >> 3, l8 = lane & 7;

    float acc[4][4][4];
    #pragma unroll
    for (int mi=0; mi<4; mi++)
        #pragma unroll
        for (int ni=0; ni<4; ni++)
            #pragma unroll
            for (int r=0; r<4; r++) acc[mi][ni][r] = 0.f;

    const int nk = Kdim / GBK;
    #pragma unroll
    for (int s = 0; s < 3; s++){
        int k0 = s * GBK;
        cp16(&As[(s*GBM + ldRow)*GST + ldOff],     Ap + k0);
        cp16(&As[(s*GBM + ldRow)*GST + ldOff + 8], Ap + k0 + 8);
        cp16(&Bs[(s*GBN + ldRow)*GST + ldOff],     Bp + k0);
        cp16(&Bs[(s*GBN + ldRow)*GST + ldOff + 8], Bp + k0 + 8);
        cp_commit();
    }

    for (int it = 0; it < nk; ++it){
        const int st = it % GSTAGES;
        if (it == nk - 1)      cp_wait<0>();
        else if (it == nk - 2) cp_wait<1>();
        else                   cp_wait<2>();
        __syncthreads();
        if (it + 3 < nk){
            int sn = (it + 3) % GSTAGES;
            int k0 = (it + 3) * GBK;
            cp16(&As[(sn*GBM + ldRow)*GST + ldOff],     Ap + k0);
            cp16(&As[(sn*GBM + ldRow)*GST + ldOff + 8], Ap + k0 + 8);
            cp16(&Bs[(sn*GBN + ldRow)*GST + ldOff],     Bp + k0);
            cp16(&Bs[(sn*GBN + ldRow)*GST + ldOff + 8], Bp + k0 + 8);
            cp_commit();
        }

        #pragma unroll
        for (int ks = 0; ks < 2; ks++){
            const int kk = ks * 16;
            uint32_t a[4][4], bq[2][4];
            #pragma unroll
            for (int mi = 0; mi < 4; mi++)
                ldsm4(a[mi], &As[(st*GBM + wm + mi*16 + l16)*GST + kk + lh*8]);
            #pragma unroll
            for (int ni2 = 0; ni2 < 2; ni2++)
                ldsm4(bq[ni2], &Bs[(st*GBN + wn + ni2*16 + (g8h>>1)*8 + l8)*GST + kk + (g8h&1)*8]);
            #pragma unroll
            for (int mi = 0; mi < 4; mi++)
                #pragma unroll
                for (int ni = 0; ni < 4; ni++)
                    mma16816(acc[mi][ni], a[mi], &bq[ni>>1][(ni&1)*2]);
        }
        // single barrier per iter (writer targets stage (it+3)%4 == (it-1)%4)
    }

    if (mode == 0){
        #pragma unroll
        for (int mi = 0; mi < 4; mi++)
            #pragma unroll
            for (int ni = 0; ni < 4; ni++){
                int r = bm + wm + mi*16 + (lane >> 2);
                int c = bn + wn + ni*8 + (lane & 3)*2;
                *(float2*)&C[(size_t)r*Ndim + c]     = make_float2(acc[mi][ni][0], acc[mi][ni][1]);
                *(float2*)&C[(size_t)(r+8)*Ndim + c] = make_float2(acc[mi][ni][2], acc[mi][ni][3]);
            }
    } else if (bn < 2048){
        // Q region -> half
        #pragma unroll
        for (int mi = 0; mi < 4; mi++)
            #pragma unroll
            for (int ni = 0; ni < 4; ni++){
                int r = bm + wm + mi*16 + (lane >> 2);
                int c = bn + wn + ni*8 + (lane & 3)*2;
                int bb = r >> 11;
                int hh = c >> 6, dd = c & 63;
                size_t base = (((size_t)bb*H_ + hh)*S_ + (r & (S_-1)))*D_ + dd;
                *(__half2*)&Cq[base] = __halves2half2(__float2half_rn(acc[mi][ni][0]),
                                                      __float2half_rn(acc[mi][ni][1]));
                size_t base2 = (((size_t)bb*H_ + hh)*S_ + ((r+8) & (S_-1)))*D_ + dd;
                *(__half2*)&Cq[base2] = __halves2half2(__float2half_rn(acc[mi][ni][2]),
                                                       __float2half_rn(acc[mi][ni][3]));
            }
    } else {
        float* T; int nb;
        if (bn < 2560) { T = Ck; nb = 2048; }
        else           { T = Cv; nb = 2560; }
        #pragma unroll
        for (int mi = 0; mi < 4; mi++)
            #pragma unroll
            for (int ni = 0; ni < 4; ni++){
                int r = bm + wm + mi*16 + (lane >> 2);
                int c = bn + wn + ni*8 + (lane & 3)*2 - nb;
                int bb = r >> 11;
                int hh = c >> 6, dd = c & 63;
                size_t base = (((size_t)bb*G_ + hh)*S_ + (r & (S_-1)))*D_ + dd;
                *(float2*)&T[base] = make_float2(acc[mi][ni][0], acc[mi][ni][1]);
                size_t base2 = (((size_t)bb*G_ + hh)*S_ + ((r+8) & (S_-1)))*D_ + dd;
                *(float2*)&T[base2] = make_float2(acc[mi][ni][2], acc[mi][ni][3]);
            }
    }
}

// ---------------- fused RMSNorm + RoPE (float input) ----------------
__global__ void rmsrope2_kernel(const float* __restrict__ in, float* __restrict__ outf,
                                __half* __restrict__ outh,
                                const float* __restrict__ cosp, const float* __restrict__ sinp,
                                const float* __restrict__ scale, int totalRows, float mult)
{
    int row  = blockIdx.x * (blockDim.x >> 5) + (threadIdx.x >> 5);
    int lane = threadIdx.x & 31;
    if (row >= totalRows) return;
    int s = row & (S_ - 1);
    const float* p = in + (size_t)row * D_;
    float v1 = p[lane], v2 = p[lane + 32];
    float ss = v1*v1 + v2*v2;
    #pragma unroll
    for (int o = 16; o > 0; o >>= 1) ss += __shfl_xor_sync(0xffffffffu, ss, o);
    float inv = rsqrtf(ss * (1.0f/64.0f) + 1e-6f);
    float n1 = v1 * inv * scale[lane];
    float n2 = v2 * inv * scale[lane + 32];
    float c1 = cosp[s*D_ + lane],      s1 = sinp[s*D_ + lane];
    float c2 = cosp[s*D_ + lane + 32], s2 = sinp[s*D_ + lane + 32];
    float o1 = n1*c1 - n2*s1;
    float o2 = n2*c2 + n1*s2;
    if (outf){
        outf[(size_t)row*D_ + lane]      = o1;
        outf[(size_t)row*D_ + lane + 32] = o2;
    }
    outh[(size_t)row*D_ + lane]      = __float2half_rn(o1 * mult);
    outh[(size_t)row*D_ + lane + 32] = __float2half_rn(o2 * mult);
}

// ---------------- fused RMSNorm + RoPE (half input) ----------------
__global__ void rmsropeh_kernel(const __half* __restrict__ in, __half* __restrict__ outh,
                                const float* __restrict__ cosp, const float* __restrict__ sinp,
                                const float* __restrict__ scale, int totalRows, float mult)
{
    int row  = blockIdx.x * (blockDim.x >> 5) + (threadIdx.x >> 5);
    int lane = threadIdx.x & 31;
    if (row >= totalRows) return;
    int s = row & (S_ - 1);
    const __half* p = in + (size_t)row * D_;
    float v1 = __half2float(p[lane]), v2 = __half2float(p[lane + 32]);
    float ss = v1*v1 + v2*v2;
    #pragma unroll
    for (int o = 16; o > 0; o >>= 1) ss += __shfl_xor_sync(0xffffffffu, ss, o);
    float inv = rsqrtf(ss * (1.0f/64.0f) + 1e-6f);
    float n1 = v1 * inv * scale[lane];
    float n2 = v2 * inv * scale[lane + 32];
    float c1 = cosp[s*D_ + lane],      s1 = sinp[s*D_ + lane];
    float c2 = cosp[s*D_ + lane + 32], s2 = sinp[s*D_ + lane + 32];
    outh[(size_t)row*D_ + lane]      = __float2half_rn((n1*c1 - n2*s1) * mult);
    outh[(size_t)row*D_ + lane + 32] = __float2half_rn((n2*c2 + n1*s2) * mult);
}

// ---------------- FA2 attention: 4-stage, LPT, forced 2 CTA/SM ----------------
#define AQP 72
#define VROWS 80
#define ASTAGES 4

__global__ __launch_bounds__(256,2) void attn3_kernel(
    const __half* __restrict__ Qh, const __half* __restrict__ Kh,
    const __half* __restrict__ Vt, __half* __restrict__ CTX)
{
    extern __shared__ char smraw[];
    __half* Qs = (__half*)smraw;
    __half* Ks = Qs + 128*AQP;
    __half* Vs = Ks + ASTAGES*64*AQP;

    const int tid = threadIdx.x, lane = tid & 31, w = tid >> 5;
    const int l16 = lane & 15, lh = lane >> 4;
    const int g8h = lane >> 3, l8 = lane & 7;

    const int qt = (int)gridDim.x - 1 - (int)blockIdx.x;
    const int bh = blockIdx.y;
    const int b = bh >> 5, h = bh & 31, g = h >> 2;

    const __half* Qbase = Qh + (((size_t)b*H_ + h)*S_ + (size_t)qt*128) * D_;
    const __half* Kbase = Kh + ((size_t)b*G_ + g) * (size_t)S_ * D_;
    const __half* Vbase = Vt + ((size_t)b*G_ + g) * (size_t)D_ * S_;

    const int nkt = 2*qt + 2;

    for (int idx = tid; idx < ASTAGES*16*AQP; idx += 256){
        int s  = idx / (16*AQP);
        int rm = idx % (16*AQP);
        int r  = rm / AQP, c = rm % AQP;
        Vs[((size_t)s*VROWS + 64 + r)*AQP + c] = (r == 0) ? __float2half(1.f) : __float2half(0.f);
    }

    {
        int r = tid >> 1, c0 = (tid & 1) * 32;
        const __half* qp = Qbase + (size_t)r*D_ + c0;
        cp16(&Qs[r*AQP + c0],      qp);
        cp16(&Qs[r*AQP + c0 + 8],  qp + 8);
        cp16(&Qs[r*AQP + c0 + 16], qp + 16);
        cp16(&Qs[r*AQP + c0 + 24], qp + 24);
        cp_commit();
        int r2 = tid >> 2, c2 = (tid & 3) * 16;
        int npre = nkt < 3 ? nkt : 3;
        for (int t = 0; t < npre; t++){
            const __half* kp = Kbase + ((size_t)t*64 + r2)*D_ + c2;
            cp16(&Ks[(t*64 + r2)*AQP + c2],     kp);
            cp16(&Ks[(t*64 + r2)*AQP + c2 + 8], kp + 8);
            const __half* vp = Vbase + (size_t)r2*S_ + (size_t)t*64 + c2;
            cp16(&Vs[(t*VROWS + r2)*AQP + c2],     vp);
            cp16(&Vs[(t*VROWS + r2)*AQP + c2 + 8], vp + 8);
            cp_commit();
        }
    }
    if (nkt >= 3) cp_wait<3>(); else cp_wait<2>();
    __syncthreads();

    uint32_t qa[4][4];
    #pragma unroll
    for (int ks = 0; ks < 4; ks++)
        ldsm4(qa[ks], &Qs[(w*16 + l16)*AQP + ks*16 + lh*8]);

    float o[9][4];
    #pragma unroll
    for (int j = 0; j < 9; j++)
        #pragma unroll
        for (int r = 0; r < 4; r++) o[j][r] = 0.f;
    float m0 = -1e30f, m1 = -1e30f;

    const int qmin = qt*128 + w*16;
    const int r2 = tid >> 2, c2l = (tid & 3) * 16;

    for (int kt = 0; kt < nkt; ++kt){
        const int st = kt % ASTAGES;
        if (kt == nkt - 1)      cp_wait<0>();
        else if (kt == nkt - 2) cp_wait<1>();
        else                    cp_wait<2>();
        __syncthreads();
        if (kt + 3 < nkt){
            int sn = (kt + 3) % ASTAGES;
            const __half* kp = Kbase + ((size_t)(kt+3)*64 + r2)*D_ + c2l;
            cp16(&Ks[(sn*64 + r2)*AQP + c2l],     kp);
            cp16(&Ks[(sn*64 + r2)*AQP + c2l + 8], kp + 8);
            const __half* vp = Vbase + (size_t)r2*S_ + (size_t)(kt+3)*64 + c2l;
            cp16(&Vs[(sn*VROWS + r2)*AQP + c2l],     vp);
            cp16(&Vs[(sn*VROWS + r2)*AQP + c2l + 8], vp + 8);
            cp_commit();
        }

        if (kt*64 <= qmin + 15){
            float sc[8][4];
            #pragma unroll
            for (int j = 0; j < 8; j++)
                #pragma unroll
                for (int r = 0; r < 4; r++) sc[j][r] = 0.f;

            #pragma unroll
            for (int ks = 0; ks < 4; ks++){
                uint32_t bq[4][4];
                #pragma unroll
                for (int nt2 = 0; nt2 < 4; nt2++)
                    ldsm4(bq[nt2], &Ks[(st*64 + nt2*16 + (g8h>>1)*8 + l8)*AQP + ks*16 + (g8h&1)*8]);
                #pragma unroll
                for (int j = 0; j < 8; j++)
                    mma16816(sc[j], qa[ks], &bq[j>>1][(j&1)*2]);
            }

            const int qg0 = qmin + (lane >> 2);
            if (kt*64 + 63 > qmin){
                #pragma unroll
                for (int j = 0; j < 8; j++){
                    int kg = kt*64 + j*8 + (lane & 3)*2;
                    if (kg     > qg0    ) sc[j][0] = -1e30f;
                    if (kg + 1 > qg0    ) sc[j][1] = -1e30f;
                    if (kg     > qg0 + 8) sc[j][2] = -1e30f;
                    if (kg + 1 > qg0 + 8) sc[j][3] = -1e30f;
                }
            }

            float mx0 = -1e30f, mx1 = -1e30f;
            #pragma unroll
            for (int j = 0; j < 8; j++){
                mx0 = fmaxf(mx0, fmaxf(sc[j][0], sc[j][1]));
                mx1 = fmaxf(mx1, fmaxf(sc[j][2], sc[j][3]));
            }
            mx0 = fmaxf(mx0, __shfl_xor_sync(0xffffffffu, mx0, 1));
            mx0 = fmaxf(mx0, __shfl_xor_sync(0xffffffffu, mx0, 2));
            mx1 = fmaxf(mx1, __shfl_xor_sync(0xffffffffu, mx1, 1));
            mx1 = fmaxf(mx1, __shfl_xor_sync(0xffffffffu, mx1, 2));
            float mn0 = fmaxf(m0, mx0), mn1 = fmaxf(m1, mx1);
            float al0 = exp2f(m0 - mn0), al1 = exp2f(m1 - mn1);
            m0 = mn0; m1 = mn1;

            uint32_t pa[4][4];
            #pragma unroll
            for (int j = 0; j < 8; j++){
                int ks = j >> 1, hi = (j & 1) * 2;
                pa[ks][hi]     = ex2h2(sc[j][0] - mn0, sc[j][1] - mn0);
                pa[ks][hi + 1] = ex2h2(sc[j][2] - mn1, sc[j][3] - mn1);
            }

            #pragma unroll
            for (int j = 0; j < 9; j++){
                o[j][0] *= al0; o[j][1] *= al0;
                o[j][2] *= al1; o[j][3] *= al1;
            }

            #pragma unroll
            for (int ks = 0; ks < 4; ks++){
                uint32_t bv[4][4], bone[4];
                #pragma unroll
                for (int nt2 = 0; nt2 < 4; nt2++)
                    ldsm4(bv[nt2], &Vs[(st*VROWS + nt2*16 + (g8h>>1)*8 + l8)*AQP + ks*16 + (g8h&1)*8]);
                ldsm4(bone, &Vs[(st*VROWS + 64 + (g8h>>1)*8 + l8)*AQP + ks*16 + (g8h&1)*8]);
                #pragma unroll
                for (int j = 0; j < 8; j++)
                    mma16816(o[j], pa[ks], &bv[j>>1][(j&1)*2]);
                mma16816(o[8], pa[ks], &bone[0]);
            }
        }
    }

    int src = lane & ~3;
    float l0 = __shfl_sync(0xffffffffu, o[8][0], src);
    float l1 = __shfl_sync(0xffffffffu, o[8][2], src);
    float i0 = 1.0f / l0, i1 = 1.0f / l1;

    const int q0 = w*16 + (lane >> 2);
    const int sg0 = qt*128 + q0;
    #pragma unroll
    for (int j = 0; j < 8; j++){
        int d = j*8 + (lane & 3)*2;
        __half2 hA = __halves2half2(__float2half_rn(o[j][0]*i0), __float2half_rn(o[j][1]*i0));
        __half2 hB = __halves2half2(__float2half_rn(o[j][2]*i1), __float2half_rn(o[j][3]*i1));
        *(__half2*)&CTX[(((size_t)b*S_ + sg0    )*H_ + h)*D_ + d] = hA;
        *(__half2*)&CTX[(((size_t)b*S_ + sg0 + 8)*H_ + h)*D_ + d] = hB;
    }
}

// ---------------- launch ----------------
extern "C" void kernel_launch(void* const* d_in, const int* in_sizes, int n_in,
                              void* d_out, int out_size)
{
    const float* x      = (const float*)d_in[0];
    const float* cosp   = (const float*)d_in[2];
    const float* sinp   = (const float*)d_in[3];
    const float* Wq     = (const float*)d_in[4];
    const float* Wk     = (const float*)d_in[5];
    const float* Wv     = (const float*)d_in[6];
    const float* Wo     = (const float*)d_in[7];
    const float* qscale = (const float*)d_in[8];
    const float* kscale = (const float*)d_in[9];

    float* out  = (float*)d_out;
    float* Kout = out + OUT_ELEMS;
    float* Vout = Kout + KV_ELEMS;

    __half *xh, *Wqkvt, *Wot, *Qraw, *Qh, *Kh, *Vt, *ctxh;
    cudaGetSymbolAddress((void**)&xh,    g_xh);
    cudaGetSymbolAddress((void**)&Wqkvt, g_Wqkvt);
    cudaGetSymbolAddress((void**)&Wot,   g_Wot);
    cudaGetSymbolAddress((void**)&Qraw,  g_Qraw);
    cudaGetSymbolAddress((void**)&Qh,    g_Qh);
    cudaGetSymbolAddress((void**)&Kh,    g_Kh);
    cudaGetSymbolAddress((void**)&Vt,    g_Vt);
    cudaGetSymbolAddress((void**)&ctxh,  g_ctxh);

    const int gemmSmem = 2 * GSTAGES * GBM * GST * (int)sizeof(__half);  // 81920
    cudaFuncSetAttribute(hgemm_kernel, cudaFuncAttributeMaxDynamicSharedMemorySize, gemmSmem);

    {
        int n4 = (M_*DIN_)/4;
        f2h_kernel<<<(n4+255)/256, 256>>>(x, xh, n4);
        dim3 tb(32,8);
        wtrans_kernel<<<dim3((H_*D_)/32, DIN_/32), tb>>>(Wq, Wqkvt,                     DIN_, H_*D_);
        wtrans_kernel<<<dim3((G_*D_)/32, DIN_/32), tb>>>(Wk, Wqkvt + (size_t)2048*DIN_, DIN_, G_*D_);
        wtrans_kernel<<<dim3((G_*D_)/32, DIN_/32), tb>>>(Wv, Wqkvt + (size_t)2560*DIN_, DIN_, G_*D_);
        wtrans_kernel<<<dim3(DIN_/32, (H_*D_)/32), tb>>>(Wo, Wot, H_*D_, DIN_);
    }

    // fused QKV projection (Q -> half, K/V -> float outputs)
    hgemm_kernel<<<dim3(3072/GBN, M_/GBM), 256, gemmSmem>>>(
        xh, Wqkvt, nullptr, Kout, Vout, Qraw, 3072, DIN_, 2);

    // rmsnorm + rope; Q additionally scaled by log2e/sqrt(D)
    rmsropeh_kernel<<<(B_*H_*S_)/8, 256>>>(Qraw, Qh, cosp, sinp, qscale, B_*H_*S_, 0.125f*1.44269504089f);
    rmsrope2_kernel<<<(B_*G_*S_)/8, 256>>>(Kout, Kout, Kh, cosp, sinp, kscale, B_*G_*S_, 1.0f);
    vtrans_kernel<<<dim3(S_/32, D_/32, B_*G_), dim3(32,8)>>>(Vout, Vt);

    // attention
    {
        int smem = (128*AQP + ASTAGES*64*AQP + ASTAGES*VROWS*AQP) * (int)sizeof(__half);  // 101376
        cudaFuncSetAttribute(attn3_kernel, cudaFuncAttributeMaxDynamicSharedMemorySize, smem);
        attn3_kernel<<<dim3(S_/128, B_*H_), 256, smem>>>(Qh, Kh, Vt, ctxh);
    }

    // output projection
    hgemm_kernel<<<dim3(DIN_/GBN, M_/GBM), 256, gemmSmem>>>(
        ctxh, Wot, out, nullptr, nullptr, nullptr, DIN_, H_*D_, 0);
}